// round 2
// baseline (speedup 1.0000x reference)
#include <cuda_runtime.h>

// Problem constants (fixed by the dataset)
#define Bn 16384
#define Sn 512
#define Pn 1024
#define Kn 8
#define Dn 64
#define Hn 128
#define TB 32   // b-rows per block in the output kernel

// Intermediates (device globals -- no allocation allowed)
__device__ float g_att[Pn * Kn];
__device__ int   g_idx[Pn * Kn];

// ---------------------------------------------------------------------------
// Kernel 1: per-problem attention weights.
// One block per p (1024 blocks, 128 threads = one per h).
//   scores[p,k] = sum_h v[h] * tanh( (plm_emd[p] . W[h]) + (skl_emd[s_k] . U[h]) )
//   att = softmax_k(scores)
// group_idx dtype is auto-detected (int32 vs int64) from the first 16 words:
// JAX with x64 disabled silently emits int32 even though the ref says int64.
// ---------------------------------------------------------------------------
__global__ __launch_bounds__(128) void score_kernel(
    const float* __restrict__ skl_emd,
    const float* __restrict__ plm_emd,
    const float* __restrict__ W,
    const float* __restrict__ U,
    const float* __restrict__ v,
    const int* __restrict__ gidx32)   // raw words of group_idx buffer
{
    const int p    = blockIdx.x;
    const int tid  = threadIdx.x;
    const int lane = tid & 31;
    const int wid  = tid >> 5;

    __shared__ __align__(16) float e8[Kn][Dn];   // gathered skill rows
    __shared__ __align__(16) float pe[Dn];       // plm row
    __shared__ int   si[Kn];
    __shared__ int   is64_s;
    __shared__ float red[Kn][4];

    // dtype detection: int64 little-endian => odd words (high halves) all zero.
    if (tid == 0) {
        int odd_or = 0;
        #pragma unroll
        for (int i = 1; i < 16; i += 2) odd_or |= gidx32[i];
        is64_s = (odd_or == 0);
    }
    __syncthreads();
    const int is64 = is64_s;

    if (tid < Kn) {
        const int pos = p * Kn + tid;
        si[tid] = is64 ? gidx32[2 * pos] : gidx32[pos];   // low word if int64
    }
    if (tid < Dn) pe[tid] = plm_emd[p * Dn + tid];
    __syncthreads();

    for (int i = tid; i < Kn * Dn; i += 128)
        e8[i >> 6][i & 63] = skl_emd[si[i >> 6] * Dn + (i & 63)];

    // W row of this h -> registers, compute proj_p contribution
    float wr[Dn];
    #pragma unroll
    for (int i = 0; i < Dn / 4; i++) {
        float4 t = reinterpret_cast<const float4*>(W)[tid * (Dn / 4) + i];
        wr[4*i] = t.x; wr[4*i+1] = t.y; wr[4*i+2] = t.z; wr[4*i+3] = t.w;
    }
    float pp = 0.f;
    #pragma unroll
    for (int i = 0; i < Dn / 4; i++) {
        float4 t = reinterpret_cast<const float4*>(pe)[i];
        pp += t.x*wr[4*i] + t.y*wr[4*i+1] + t.z*wr[4*i+2] + t.w*wr[4*i+3];
    }
    // Reuse the same registers for the U row
    #pragma unroll
    for (int i = 0; i < Dn / 4; i++) {
        float4 t = reinterpret_cast<const float4*>(U)[tid * (Dn / 4) + i];
        wr[4*i] = t.x; wr[4*i+1] = t.y; wr[4*i+2] = t.z; wr[4*i+3] = t.w;
    }
    const float vh = v[tid];
    __syncthreads();

    #pragma unroll
    for (int k = 0; k < Kn; k++) {
        float ps = 0.f;
        #pragma unroll
        for (int i = 0; i < Dn / 4; i++) {
            float4 t = reinterpret_cast<const float4*>(e8[k])[i];
            ps += t.x*wr[4*i] + t.y*wr[4*i+1] + t.z*wr[4*i+2] + t.w*wr[4*i+3];
        }
        float t = tanhf(pp + ps) * vh;
        #pragma unroll
        for (int off = 16; off > 0; off >>= 1)
            t += __shfl_down_sync(0xffffffffu, t, off);
        if (lane == 0) red[k][wid] = t;
    }
    __syncthreads();

    if (tid == 0) {
        float s[Kn], m = -1e30f;
        #pragma unroll
        for (int k = 0; k < Kn; k++) {
            s[k] = red[k][0] + red[k][1] + red[k][2] + red[k][3];
            m = fmaxf(m, s[k]);
        }
        float ex[Kn], sum = 0.f;
        #pragma unroll
        for (int k = 0; k < Kn; k++) { ex[k] = expf(s[k] - m); sum += ex[k]; }
        const float inv = 1.f / sum;
        #pragma unroll
        for (int k = 0; k < Kn; k++) {
            g_att[p * Kn + k] = ex[k] * inv;
            g_idx[p * Kn + k] = si[k];
        }
    }
}

// ---------------------------------------------------------------------------
// Kernel 2: the heavy pass.
//   out[b,p] = mask[b,p] * sum_k pfc_s[b][idx[p,k]] * att[p,k]
// Grid (Pn/256, Bn/TB). Threads are p-lanes -> mask/out fully coalesced.
// TB=32 skl_pfc rows staged in 64 KB SMEM; per-thread idx/att registers are
// amortized over all TB b-rows. Gathers are random-bank LDS (~4-way expected).
// ---------------------------------------------------------------------------
__global__ __launch_bounds__(256) void out_kernel(
    const float* __restrict__ pfc,
    const float* __restrict__ mask,
    float* __restrict__ out)
{
    extern __shared__ float pfc_s[];   // [TB][Sn]
    const int tid = threadIdx.x;
    const int p   = blockIdx.x * 256 + tid;
    const int b0  = blockIdx.y * TB;

    // Stage TB contiguous skl_pfc rows (coalesced float4, conflict-free STS)
    const float4* src = reinterpret_cast<const float4*>(pfc + (size_t)b0 * Sn);
    float4*       dst = reinterpret_cast<float4*>(pfc_s);
    #pragma unroll
    for (int i = tid; i < TB * Sn / 4; i += 256) dst[i] = src[i];

    // Per-p attention table -> registers (L2-resident, coalesced int4/float4)
    int idx[Kn]; float att[Kn];
    {
        int4   i0 = reinterpret_cast<const int4*>(g_idx)[p * 2];
        int4   i1 = reinterpret_cast<const int4*>(g_idx)[p * 2 + 1];
        float4 a0 = reinterpret_cast<const float4*>(g_att)[p * 2];
        float4 a1 = reinterpret_cast<const float4*>(g_att)[p * 2 + 1];
        idx[0]=i0.x; idx[1]=i0.y; idx[2]=i0.z; idx[3]=i0.w;
        idx[4]=i1.x; idx[5]=i1.y; idx[6]=i1.z; idx[7]=i1.w;
        att[0]=a0.x; att[1]=a0.y; att[2]=a0.z; att[3]=a0.w;
        att[4]=a1.x; att[5]=a1.y; att[6]=a1.z; att[7]=a1.w;
    }
    __syncthreads();

    #pragma unroll 4
    for (int b = 0; b < TB; b++) {
        const float* row = pfc_s + b * Sn;
        float acc = row[idx[0]] * att[0];
        acc += row[idx[1]] * att[1];
        acc += row[idx[2]] * att[2];
        acc += row[idx[3]] * att[3];
        acc += row[idx[4]] * att[4];
        acc += row[idx[5]] * att[5];
        acc += row[idx[6]] * att[6];
        acc += row[idx[7]] * att[7];
        const int o = (b0 + b) * Pn + p;
        out[o] = acc * mask[o];
    }
}

// ---------------------------------------------------------------------------
// Launch. Inputs (metadata order): skl_pfc, tensor_mask, skl_emd, plm_emd,
// W, U, v_T, group_idx. Output: [B, P] float32.
// ---------------------------------------------------------------------------
extern "C" void kernel_launch(void* const* d_in, const int* in_sizes, int n_in,
                              void* d_out, int out_size)
{
    const float* skl_pfc     = (const float*)d_in[0];
    const float* tensor_mask = (const float*)d_in[1];
    const float* skl_emd     = (const float*)d_in[2];
    const float* plm_emd     = (const float*)d_in[3];
    const float* W           = (const float*)d_in[4];
    const float* U           = (const float*)d_in[5];
    const float* v           = (const float*)d_in[6];
    const int*   gidx32      = (const int*)d_in[7];   // int32 or int64 words, auto-detected
    float*       out         = (float*)d_out;

    score_kernel<<<Pn, 128>>>(skl_emd, plm_emd, W, U, v, gidx32);

    const int smem = TB * Sn * (int)sizeof(float);   // 64 KB
    cudaFuncSetAttribute(out_kernel, cudaFuncAttributeMaxDynamicSharedMemorySize, smem);
    dim3 grid(Pn / 256, Bn / TB);
    out_kernel<<<grid, 256, smem>>>(skl_pfc, tensor_mask, out);
}

// round 7
// speedup vs baseline: 2.0535x; 2.0535x over previous
#include <cuda_runtime.h>
#include <cuda_fp16.h>

// Problem constants (fixed by the dataset)
#define Bn 16384
#define Sn 512
#define Pn 1024
#define Kn 8
#define Dn 64
#define Hn 128
#define TBo 64        // b-rows per out-kernel block (8 groups of 8)

// Intermediates (device globals -- no allocation allowed)
__device__ float g_att[Pn * Kn];
__device__ int   g_idx[Pn * Kn];

// ---------------------------------------------------------------------------
// Kernel 1: per-problem attention weights (identical to the R2 passing version).
//   scores[p,k] = sum_h v[h] * tanh( (plm_emd[p].W[h]) + (skl_emd[s_k].U[h]) )
//   att = softmax_k(scores)
// group_idx dtype auto-detected (int32 vs int64) from the first 16 words.
// ---------------------------------------------------------------------------
__global__ __launch_bounds__(128) void score_kernel(
    const float* __restrict__ skl_emd,
    const float* __restrict__ plm_emd,
    const float* __restrict__ W,
    const float* __restrict__ U,
    const float* __restrict__ v,
    const int* __restrict__ gidx32)
{
    const int p    = blockIdx.x;
    const int tid  = threadIdx.x;
    const int lane = tid & 31;
    const int wid  = tid >> 5;

    __shared__ __align__(16) float e8[Kn][Dn];
    __shared__ __align__(16) float pe[Dn];
    __shared__ int   si[Kn];
    __shared__ int   is64_s;
    __shared__ float red[Kn][4];

    if (tid == 0) {
        int odd_or = 0;
        #pragma unroll
        for (int i = 1; i < 16; i += 2) odd_or |= gidx32[i];
        is64_s = (odd_or == 0);
    }
    __syncthreads();
    const int is64 = is64_s;

    if (tid < Kn) {
        const int pos = p * Kn + tid;
        si[tid] = is64 ? gidx32[2 * pos] : gidx32[pos];
    }
    if (tid < Dn) pe[tid] = plm_emd[p * Dn + tid];
    __syncthreads();

    for (int i = tid; i < Kn * Dn; i += 128)
        e8[i >> 6][i & 63] = skl_emd[si[i >> 6] * Dn + (i & 63)];

    float wr[Dn];
    #pragma unroll
    for (int i = 0; i < Dn / 4; i++) {
        float4 t = reinterpret_cast<const float4*>(W)[tid * (Dn / 4) + i];
        wr[4*i] = t.x; wr[4*i+1] = t.y; wr[4*i+2] = t.z; wr[4*i+3] = t.w;
    }
    float pp = 0.f;
    #pragma unroll
    for (int i = 0; i < Dn / 4; i++) {
        float4 t = reinterpret_cast<const float4*>(pe)[i];
        pp += t.x*wr[4*i] + t.y*wr[4*i+1] + t.z*wr[4*i+2] + t.w*wr[4*i+3];
    }
    #pragma unroll
    for (int i = 0; i < Dn / 4; i++) {
        float4 t = reinterpret_cast<const float4*>(U)[tid * (Dn / 4) + i];
        wr[4*i] = t.x; wr[4*i+1] = t.y; wr[4*i+2] = t.z; wr[4*i+3] = t.w;
    }
    const float vh = v[tid];
    __syncthreads();

    #pragma unroll
    for (int k = 0; k < Kn; k++) {
        float ps = 0.f;
        #pragma unroll
        for (int i = 0; i < Dn / 4; i++) {
            float4 t = reinterpret_cast<const float4*>(e8[k])[i];
            ps += t.x*wr[4*i] + t.y*wr[4*i+1] + t.z*wr[4*i+2] + t.w*wr[4*i+3];
        }
        float t = tanhf(pp + ps) * vh;
        #pragma unroll
        for (int off = 16; off > 0; off >>= 1)
            t += __shfl_down_sync(0xffffffffu, t, off);
        if (lane == 0) red[k][wid] = t;
    }
    __syncthreads();

    if (tid == 0) {
        float s[Kn], m = -1e30f;
        #pragma unroll
        for (int k = 0; k < Kn; k++) {
            s[k] = red[k][0] + red[k][1] + red[k][2] + red[k][3];
            m = fmaxf(m, s[k]);
        }
        float ex[Kn], sum = 0.f;
        #pragma unroll
        for (int k = 0; k < Kn; k++) { ex[k] = expf(s[k] - m); sum += ex[k]; }
        const float inv = 1.f / sum;
        #pragma unroll
        for (int k = 0; k < Kn; k++) {
            g_att[p * Kn + k] = ex[k] * inv;
            g_idx[p * Kn + k] = si[k];
        }
    }
}

// ---------------------------------------------------------------------------
// Kernel 2: the heavy pass with in-kernel fp16x8 packing.
//
// Block = 512 threads, one 64-b tile. Layout sh[s][64 halves]: per s, eight
// 16B groups of 8 consecutive b's, group g stored at slot = g ^ ((s^(s>>3))&7).
//  * Pack: thread (g = tid>>6, sq = tid&63) loads rows b = g*8..g*8+7 over
//    s = sq*8..sq*8+7 (float4 pairs, warp-contiguous 1024B span per row),
//    converts to fp16, stores 8 STS.128. The (s>>3)&7 = lane&7 term of the
//    swizzle makes each 8-lane store phase hit 8 distinct bank quads
//    (conflict-free STS) while keeping gather-side spread random in s.
//  * Gather: thread serves p = tid and p+512. One LDS.128 yields 8 b-terms:
//      out[b,p] = mask[b,p] * sum_k pfc16[b][idx[p,k]] * att[p,k]
// ---------------------------------------------------------------------------
__global__ __launch_bounds__(512) void out_kernel(
    const float* __restrict__ pfc,
    const float* __restrict__ mask,
    float* __restrict__ out)
{
    extern __shared__ __half sh[];   // [Sn][64] halves, groups swizzled
    const int tid = threadIdx.x;
    const int t   = blockIdx.x;      // b-tile (64 b's)

    // ---- Pack phase ----
    {
        const int sq = tid & 63;     // s-octet: s = sq*8 + i
        const int g  = tid >> 6;     // b-group 0..7
        __half h[8][8];              // [i][j] : s = sq*8+i, b = g*8+j
        #pragma unroll
        for (int j = 0; j < 8; j++) {
            const float* rp = pfc + ((size_t)t * 64 + g * 8 + j) * Sn + sq * 8;
            float4 f0 = *reinterpret_cast<const float4*>(rp);
            float4 f1 = *reinterpret_cast<const float4*>(rp + 4);
            h[0][j] = __float2half_rn(f0.x); h[1][j] = __float2half_rn(f0.y);
            h[2][j] = __float2half_rn(f0.z); h[3][j] = __float2half_rn(f0.w);
            h[4][j] = __float2half_rn(f1.x); h[5][j] = __float2half_rn(f1.y);
            h[6][j] = __float2half_rn(f1.z); h[7][j] = __float2half_rn(f1.w);
        }
        #pragma unroll
        for (int i = 0; i < 8; i++) {
            const int s    = sq * 8 + i;
            const int slot = g ^ ((s ^ (s >> 3)) & 7);
            __half2 p01 = __halves2half2(h[i][0], h[i][1]);
            __half2 p23 = __halves2half2(h[i][2], h[i][3]);
            __half2 p45 = __halves2half2(h[i][4], h[i][5]);
            __half2 p67 = __halves2half2(h[i][6], h[i][7]);
            uint4 w;
            w.x = *reinterpret_cast<unsigned int*>(&p01);
            w.y = *reinterpret_cast<unsigned int*>(&p23);
            w.z = *reinterpret_cast<unsigned int*>(&p45);
            w.w = *reinterpret_cast<unsigned int*>(&p67);
            *reinterpret_cast<uint4*>(sh + s * 64 + slot * 8) = w;
        }
    }
    __syncthreads();

    // ---- Gather phase: this thread serves p = tid and p = tid + 512 ----
    #pragma unroll
    for (int pi = 0; pi < 2; pi++) {
        const int p = tid + pi * 512;

        int idx[Kn]; float att[Kn];
        {
            int4   i0 = reinterpret_cast<const int4*>(g_idx)[p * 2];
            int4   i1 = reinterpret_cast<const int4*>(g_idx)[p * 2 + 1];
            float4 a0 = reinterpret_cast<const float4*>(g_att)[p * 2];
            float4 a1 = reinterpret_cast<const float4*>(g_att)[p * 2 + 1];
            idx[0]=i0.x; idx[1]=i0.y; idx[2]=i0.z; idx[3]=i0.w;
            idx[4]=i1.x; idx[5]=i1.y; idx[6]=i1.z; idx[7]=i1.w;
            att[0]=a0.x; att[1]=a0.y; att[2]=a0.z; att[3]=a0.w;
            att[4]=a1.x; att[5]=a1.y; att[6]=a1.z; att[7]=a1.w;
        }

        for (int g = 0; g < 8; g++) {    // 8 b-groups of 8
            float acc[8] = {0,0,0,0,0,0,0,0};
            #pragma unroll
            for (int k = 0; k < Kn; k++) {
                const int s    = idx[k];
                const int slot = g ^ ((s ^ (s >> 3)) & 7);
                const uint4 hv = *reinterpret_cast<const uint4*>(
                    sh + s * 64 + slot * 8);
                const float a = att[k];
                float2 f;
                f = __half22float2(*reinterpret_cast<const __half2*>(&hv.x));
                acc[0] += a * f.x; acc[1] += a * f.y;
                f = __half22float2(*reinterpret_cast<const __half2*>(&hv.y));
                acc[2] += a * f.x; acc[3] += a * f.y;
                f = __half22float2(*reinterpret_cast<const __half2*>(&hv.z));
                acc[4] += a * f.x; acc[5] += a * f.y;
                f = __half22float2(*reinterpret_cast<const __half2*>(&hv.w));
                acc[6] += a * f.x; acc[7] += a * f.y;
            }
            const int b0 = t * TBo + g * 8;
            #pragma unroll
            for (int j = 0; j < 8; j++) {
                const size_t o = (size_t)(b0 + j) * Pn + p;
                out[o] = acc[j] * mask[o];
            }
        }
    }
}

// ---------------------------------------------------------------------------
// Launch. Inputs (metadata order): skl_pfc, tensor_mask, skl_emd, plm_emd,
// W, U, v_T, group_idx. Output: [B, P] float32.
// ---------------------------------------------------------------------------
extern "C" void kernel_launch(void* const* d_in, const int* in_sizes, int n_in,
                              void* d_out, int out_size)
{
    const float* skl_pfc     = (const float*)d_in[0];
    const float* tensor_mask = (const float*)d_in[1];
    const float* skl_emd     = (const float*)d_in[2];
    const float* plm_emd     = (const float*)d_in[3];
    const float* W           = (const float*)d_in[4];
    const float* U           = (const float*)d_in[5];
    const float* v           = (const float*)d_in[6];
    const int*   gidx32      = (const int*)d_in[7];
    float*       out         = (float*)d_out;

    score_kernel<<<Pn, 128>>>(skl_emd, plm_emd, W, U, v, gidx32);

    const int smem = Sn * 64 * (int)sizeof(__half);   // 64 KB
    cudaFuncSetAttribute(out_kernel, cudaFuncAttributeMaxDynamicSharedMemorySize, smem);
    out_kernel<<<Bn / TBo, 512, smem>>>(skl_pfc, tensor_mask, out);
}